// round 14
// baseline (speedup 1.0000x reference)
#include <cuda_runtime.h>
#include <cuda_fp16.h>
#include <math.h>

#define BB 8
#define NN 4096
#define MM 4096
#define DD 128
#define STAGE_BYTES 32768     // 2 mats * 128 rows * 128B (64 fp16 cols)
#define NSTAGE 2
#define SMEM_TOTAL (NSTAGE * STAGE_BYTES)

// ---------------- scratch ----------------
__device__ float g_rowmin[BB * NN];
__device__ float g_colmin[BB * MM];
__device__ unsigned g_rowcnt[BB * NN];
__device__ unsigned g_colcnt[BB * MM];
__device__ float g_x2[BB * NN];
__device__ float g_y2[BB * MM];
__device__ float g_sum;
__device__ unsigned g_done;
__device__ __half g_xh[(size_t)BB * NN * DD];
__device__ __half g_yh[(size_t)BB * MM * DD];

// Four rows per warp: fp32 norms (exact), min/counter-init, fp16 conversion.
__global__ void norms_conv_kernel(const float* __restrict__ x, const float* __restrict__ y) {
    int gw   = (blockIdx.x * blockDim.x + threadIdx.x) >> 5;   // 0..16383
    int lane = threadIdx.x & 31;
    const float* src;
    float* dst;
    float* mins;
    unsigned* cnts;
    __half* dsth;
    int r0;
    if (gw < (BB * NN) / 4) {
        src = x; dst = g_x2; mins = g_rowmin; cnts = g_rowcnt; dsth = g_xh; r0 = 4 * gw;
    } else {
        src = y; dst = g_y2; mins = g_colmin; cnts = g_colcnt; dsth = g_yh;
        r0 = 4 * (gw - (BB * NN) / 4);
    }

    float4 v[4];
    #pragma unroll
    for (int k = 0; k < 4; k++)
        v[k] = *reinterpret_cast<const float4*>(src + (size_t)(r0 + k) * DD + lane * 4);

    float s[4];
    #pragma unroll
    for (int k = 0; k < 4; k++)
        s[k] = v[k].x * v[k].x + v[k].y * v[k].y + v[k].z * v[k].z + v[k].w * v[k].w;
    #pragma unroll
    for (int o = 16; o; o >>= 1) {
        #pragma unroll
        for (int k = 0; k < 4; k++)
            s[k] += __shfl_xor_sync(0xFFFFFFFFu, s[k], o);
    }

    #pragma unroll
    for (int k = 0; k < 4; k++) {
        __half2 h0 = __floats2half2_rn(v[k].x, v[k].y);
        __half2 h1 = __floats2half2_rn(v[k].z, v[k].w);
        uint2 u;
        u.x = *reinterpret_cast<unsigned*>(&h0);
        u.y = *reinterpret_cast<unsigned*>(&h1);
        *reinterpret_cast<uint2*>(dsth + (size_t)(r0 + k) * DD + lane * 4) = u;
    }

    if (lane < 4) {
        dst[r0 + lane]  = s[lane];
        mins[r0 + lane] = __int_as_float(0x7F800000);
        cnts[r0 + lane] = 0u;
    }
    if (blockIdx.x == 0 && threadIdx.x == 0) {
        g_sum  = 0.0f;
        g_done = 0u;
    }
}

// ---------------- device helpers ----------------
__device__ __forceinline__ unsigned smem_u32(const void* p) {
    unsigned a;
    asm("{ .reg .u64 t; cvta.to.shared.u64 t, %1; cvt.u32.u64 %0, t; }" : "=r"(a) : "l"(p));
    return a;
}

__device__ __forceinline__ void mma_f16(float* c, const unsigned* a, unsigned b0, unsigned b1) {
    asm volatile(
        "mma.sync.aligned.m16n8k16.row.col.f32.f16.f16.f32 "
        "{%0,%1,%2,%3}, {%4,%5,%6,%7}, {%8,%9}, {%0,%1,%2,%3};"
        : "+f"(c[0]), "+f"(c[1]), "+f"(c[2]), "+f"(c[3])
        : "r"(a[0]), "r"(a[1]), "r"(a[2]), "r"(a[3]), "r"(b0), "r"(b1));
}

__device__ __forceinline__ void ldsm4(unsigned* r, unsigned addr) {
    asm volatile("ldmatrix.sync.aligned.m8n8.x4.shared.b16 {%0,%1,%2,%3}, [%4];"
                 : "=r"(r[0]), "=r"(r[1]), "=r"(r[2]), "=r"(r[3]) : "r"(addr));
}

// acq_rel counter increment: releases prior relaxed atomics, acquires others'.
__device__ __forceinline__ unsigned atom_inc_acqrel(unsigned* p) {
    unsigned old;
    asm volatile("atom.acq_rel.gpu.global.add.u32 %0, [%1], 1;"
                 : "=r"(old) : "l"(p) : "memory");
    return old;
}
__device__ __forceinline__ float ld_acquire_f32(const float* p) {
    float v;
    asm volatile("ld.acquire.gpu.global.f32 %0, [%1];" : "=f"(v) : "l"(p) : "memory");
    return v;
}

#define CP_ASYNC16(dst, src) \
    asm volatile("cp.async.cg.shared.global [%0], [%1], 16;" :: "r"(dst), "l"(src))
#define CP_COMMIT() asm volatile("cp.async.commit_group;" ::: "memory")
#define CP_WAIT(n)  asm volatile("cp.async.wait_group %0;" :: "n"(n) : "memory")

// ---------------- main kernel (R6/R11 core + fused final reduction) ----------------
// 128x128 tile, 256 threads (8 warps 2x4), warp tile 64x32, fp16 m16n8k16,
// fp32 accumulators. K=128 as 2 chunks of 64 fp16 (128B rows), SW128 swizzle
// byte_in_row ^= (row&7)<<4. Row/col mins via global atomicMin; the 32nd
// contributor per row finalizes sqrt into g_sum; last row finisher writes out.
__global__ __launch_bounds__(256, 2)
void chamfer_mma_kernel(float* __restrict__ out) {
    extern __shared__ char smem[];
    const unsigned sbase = smem_u32(smem);

    const int t    = threadIdx.x;
    const int lane = t & 31;
    const int wid  = t >> 5;
    const int wi   = wid >> 2;    // 0..1 (64-row slab)
    const int wj   = wid & 3;     // 0..3 (32-col slab)
    const int g    = lane >> 2;   // 0..7
    const int tig  = lane & 3;    // 0..3

    const int b    = blockIdx.z;
    const int iblk = blockIdx.x * 128;
    const int jblk = blockIdx.y * 128;

    const __half* xph = g_xh + ((size_t)b * NN + iblk) * DD;
    const __half* yph = g_yh + ((size_t)b * MM + jblk) * DD;

    const unsigned swz = (unsigned)(lane & 7) << 4;
    const int arow_base = wi * 64 + (lane & 15);
    const int brow_base = wj * 32 + (lane & 7) + ((lane & 8) ? 8 : 0);
    const unsigned khalf = (lane & 16) ? 16u : 0u;

    float acc[4][4][4];
    #pragma unroll
    for (int mt = 0; mt < 4; mt++)
        #pragma unroll
        for (int nt = 0; nt < 4; nt++)
            #pragma unroll
            for (int r = 0; r < 4; r++) acc[mt][nt][r] = 0.0f;

    #define PREFETCH(stage, chunk)                                                     \
        do {                                                                            \
            unsigned sdst = sbase + (stage) * STAGE_BYTES;                              \
            _Pragma("unroll")                                                           \
            for (int p = 0; p < 8; p++) {                                               \
                int idx = p * 256 + t;                                                  \
                int mat = p >> 2;                                                       \
                int row = (idx & 1023) >> 3;                                            \
                int c4  = idx & 7;                                                      \
                const __half* gsrc = (mat ? yph : xph) + (size_t)row * DD + (chunk) * 64 + c4 * 8; \
                unsigned d = sdst + mat * 16384 + row * 128 +                           \
                             (((unsigned)(c4 * 16)) ^ (((unsigned)(row & 7)) << 4));    \
                CP_ASYNC16(d, gsrc);                                                    \
            }                                                                           \
        } while (0)

    PREFETCH(0, 0);
    CP_COMMIT();
    PREFETCH(1, 1);
    CP_COMMIT();

    #pragma unroll
    for (int c = 0; c < 2; c++) {
        if (c == 0) CP_WAIT(1); else CP_WAIT(0);
        __syncthreads();

        const unsigned abase = sbase + c * STAGE_BYTES;
        const unsigned bbase = abase + 16384;

        #pragma unroll
        for (int ks = 0; ks < 4; ks++) {
            const unsigned k0b = ks * 32;
            unsigned af[4][4], bq[2][4];
            #pragma unroll
            for (int mt = 0; mt < 4; mt++) {
                int row = arow_base + mt * 16;
                ldsm4(af[mt], abase + row * 128 + ((k0b + khalf) ^ swz));
            }
            #pragma unroll
            for (int pr = 0; pr < 2; pr++) {
                int row = brow_base + pr * 16;
                ldsm4(bq[pr], bbase + row * 128 + ((k0b + khalf) ^ swz));
            }
            #pragma unroll
            for (int mt = 0; mt < 4; mt++)
                #pragma unroll
                for (int nt = 0; nt < 4; nt++)
                    mma_f16(acc[mt][nt], af[mt],
                            bq[nt >> 1][nt & 1], bq[nt >> 1][(nt & 1) + 2]);
        }
    }

    // ---- epilogue (R6-verified min math) ----
    float x2v[4][2], y2v[4][2];
    #pragma unroll
    for (int mt = 0; mt < 4; mt++) {
        x2v[mt][0] = g_x2[(size_t)b * NN + iblk + wi * 64 + mt * 16 + g];
        x2v[mt][1] = g_x2[(size_t)b * NN + iblk + wi * 64 + mt * 16 + g + 8];
    }
    #pragma unroll
    for (int nt = 0; nt < 4; nt++) {
        y2v[nt][0] = g_y2[(size_t)b * MM + jblk + wj * 32 + nt * 8 + 2 * tig];
        y2v[nt][1] = g_y2[(size_t)b * MM + jblk + wj * 32 + nt * 8 + 2 * tig + 1];
    }

    const float INF = __int_as_float(0x7F800000);
    float rmin[4][2], cmin[4][2];
    #pragma unroll
    for (int a_ = 0; a_ < 4; a_++) { rmin[a_][0] = rmin[a_][1] = INF; cmin[a_][0] = cmin[a_][1] = INF; }

    #pragma unroll
    for (int mt = 0; mt < 4; mt++)
        #pragma unroll
        for (int nt = 0; nt < 4; nt++)
            #pragma unroll
            for (int rr = 0; rr < 2; rr++)
                #pragma unroll
                for (int cc = 0; cc < 2; cc++) {
                    float d2 = fmaxf(x2v[mt][rr] + y2v[nt][cc] - 2.0f * acc[mt][nt][rr * 2 + cc], 0.0f);
                    rmin[mt][rr] = fminf(rmin[mt][rr], d2);
                    cmin[nt][cc] = fminf(cmin[nt][cc], d2);
                }

    #pragma unroll
    for (int mt = 0; mt < 4; mt++)
        #pragma unroll
        for (int rr = 0; rr < 2; rr++) {
            float v = rmin[mt][rr];
            v = fminf(v, __shfl_xor_sync(0xFFFFFFFFu, v, 1));
            v = fminf(v, __shfl_xor_sync(0xFFFFFFFFu, v, 2));
            rmin[mt][rr] = v;
        }
    #pragma unroll
    for (int nt = 0; nt < 4; nt++)
        #pragma unroll
        for (int cc = 0; cc < 2; cc++) {
            float v = cmin[nt][cc];
            v = fminf(v, __shfl_xor_sync(0xFFFFFFFFu, v, 4));
            v = fminf(v, __shfl_xor_sync(0xFFFFFFFFu, v, 8));
            v = fminf(v, __shfl_xor_sync(0xFFFFFFFFu, v, 16));
            cmin[nt][cc] = v;
        }

    float* rowbuf = reinterpret_cast<float*>(smem);          // [128][4]
    float* colbuf = reinterpret_cast<float*>(smem) + 512;    // [128][2]
    __syncthreads();
    if (tig == 0) {
        #pragma unroll
        for (int mt = 0; mt < 4; mt++)
            #pragma unroll
            for (int rr = 0; rr < 2; rr++)
                rowbuf[(wi * 64 + mt * 16 + g + rr * 8) * 4 + wj] = rmin[mt][rr];
    }
    if (g == 0) {
        #pragma unroll
        for (int nt = 0; nt < 4; nt++)
            #pragma unroll
            for (int cc = 0; cc < 2; cc++)
                colbuf[(wj * 32 + nt * 8 + 2 * tig + cc) * 2 + wi] = cmin[nt][cc];
    }
    __syncthreads();

    // Commit tile mins + fused finalization.
    float* minptr;
    unsigned* cntptr;
    float m;
    size_t idx;
    if (t < 128) {
        m = fminf(fminf(rowbuf[t * 4 + 0], rowbuf[t * 4 + 1]),
                  fminf(rowbuf[t * 4 + 2], rowbuf[t * 4 + 3]));
        idx = (size_t)b * NN + iblk + t;
        minptr = g_rowmin; cntptr = g_rowcnt;
    } else {
        int j = t - 128;
        m = fminf(colbuf[j * 2 + 0], colbuf[j * 2 + 1]);
        idx = (size_t)b * MM + jblk + j;
        minptr = g_colmin; cntptr = g_colcnt;
    }
    atomicMin((int*)&minptr[idx], __float_as_int(m));          // relaxed
    unsigned prior = atom_inc_acqrel(&cntptr[idx]);            // release my min / acquire others'
    if (prior == 31u) {                                        // last contributor for this row
        float fin = ld_acquire_f32(&minptr[idx]);
        atomicAdd(&g_sum, sqrtf(fin));                         // relaxed
        unsigned d = atom_inc_acqrel(&g_done);                 // release my g_sum add
        if (d == 2u * BB * NN - 1u)
            out[0] = ld_acquire_f32(&g_sum) / (float)(BB * NN);
    }
}

extern "C" void kernel_launch(void* const* d_in, const int* in_sizes, int n_in,
                              void* d_out, int out_size) {
    const float* x = (const float*)d_in[0];
    const float* y = (const float*)d_in[1];
    float* out = (float*)d_out;
    (void)in_sizes; (void)n_in; (void)out_size;

    cudaFuncSetAttribute(chamfer_mma_kernel, cudaFuncAttributeMaxDynamicSharedMemorySize, SMEM_TOTAL);

    int total_warps = (2 * BB * NN) / 4;   // 16384 warps, 4 rows each
    norms_conv_kernel<<<(total_warps * 32 + 255) / 256, 256>>>(x, y);

    dim3 grid(NN / 128, MM / 128, BB);
    chamfer_mma_kernel<<<grid, 256, SMEM_TOTAL>>>(out);
}

// round 15
// speedup vs baseline: 1.4018x; 1.4018x over previous
#include <cuda_runtime.h>
#include <cuda_fp16.h>
#include <math.h>

#define BB 8
#define NN 4096
#define MM 4096
#define DD 128
#define STAGE_BYTES 32768     // 2 mats * 128 rows * 128B (64 fp16 cols)
#define NSTAGE 2
#define SMEM_TOTAL (NSTAGE * STAGE_BYTES)

// ---------------- scratch ----------------
__device__ float g_rowmin[BB * NN];
__device__ float g_colmin[BB * MM];
__device__ float g_x2[BB * NN];
__device__ float g_y2[BB * MM];
__device__ float g_sum;
__device__ unsigned g_ticket;
__device__ __half g_xh[(size_t)BB * NN * DD];
__device__ __half g_yh[(size_t)BB * MM * DD];

// Four rows per warp: fp32 norms (exact), min-init, fp16 conversion, counter reset.
__global__ void norms_conv_kernel(const float* __restrict__ x, const float* __restrict__ y) {
    int gw   = (blockIdx.x * blockDim.x + threadIdx.x) >> 5;   // 0..16383
    int lane = threadIdx.x & 31;
    const float* src;
    float* dst;
    float* mins;
    __half* dsth;
    int r0;
    if (gw < (BB * NN) / 4) { src = x; dst = g_x2; mins = g_rowmin; dsth = g_xh; r0 = 4 * gw; }
    else { src = y; dst = g_y2; mins = g_colmin; dsth = g_yh; r0 = 4 * (gw - (BB * NN) / 4); }

    float4 v[4];
    #pragma unroll
    for (int k = 0; k < 4; k++)
        v[k] = *reinterpret_cast<const float4*>(src + (size_t)(r0 + k) * DD + lane * 4);

    float s[4];
    #pragma unroll
    for (int k = 0; k < 4; k++)
        s[k] = v[k].x * v[k].x + v[k].y * v[k].y + v[k].z * v[k].z + v[k].w * v[k].w;
    #pragma unroll
    for (int o = 16; o; o >>= 1) {
        #pragma unroll
        for (int k = 0; k < 4; k++)
            s[k] += __shfl_xor_sync(0xFFFFFFFFu, s[k], o);
    }

    #pragma unroll
    for (int k = 0; k < 4; k++) {
        __half2 h0 = __floats2half2_rn(v[k].x, v[k].y);
        __half2 h1 = __floats2half2_rn(v[k].z, v[k].w);
        uint2 u;
        u.x = *reinterpret_cast<unsigned*>(&h0);
        u.y = *reinterpret_cast<unsigned*>(&h1);
        *reinterpret_cast<uint2*>(dsth + (size_t)(r0 + k) * DD + lane * 4) = u;
    }

    if (lane < 4) {
        dst[r0 + lane]  = s[lane];
        mins[r0 + lane] = __int_as_float(0x7F800000);
    }
    if (blockIdx.x == 0 && threadIdx.x == 0) {
        g_sum = 0.0f;
        g_ticket = 0u;
    }
}

// ---------------- device helpers ----------------
__device__ __forceinline__ unsigned smem_u32(const void* p) {
    unsigned a;
    asm("{ .reg .u64 t; cvta.to.shared.u64 t, %1; cvt.u32.u64 %0, t; }" : "=r"(a) : "l"(p));
    return a;
}

__device__ __forceinline__ void mma_f16(float* c, const unsigned* a, unsigned b0, unsigned b1) {
    asm volatile(
        "mma.sync.aligned.m16n8k16.row.col.f32.f16.f16.f32 "
        "{%0,%1,%2,%3}, {%4,%5,%6,%7}, {%8,%9}, {%0,%1,%2,%3};"
        : "+f"(c[0]), "+f"(c[1]), "+f"(c[2]), "+f"(c[3])
        : "r"(a[0]), "r"(a[1]), "r"(a[2]), "r"(a[3]), "r"(b0), "r"(b1));
}

__device__ __forceinline__ void ldsm4(unsigned* r, unsigned addr) {
    asm volatile("ldmatrix.sync.aligned.m8n8.x4.shared.b16 {%0,%1,%2,%3}, [%4];"
                 : "=r"(r[0]), "=r"(r[1]), "=r"(r[2]), "=r"(r[3]) : "r"(addr));
}

#define CP_ASYNC16(dst, src) \
    asm volatile("cp.async.cg.shared.global [%0], [%1], 16;" :: "r"(dst), "l"(src))
#define CP_COMMIT() asm volatile("cp.async.commit_group;" ::: "memory")
#define CP_WAIT(n)  asm volatile("cp.async.wait_group %0;" :: "n"(n) : "memory")

// ---------------- main kernel ----------------
// 128x128 tile, 256 threads (8 warps 2x4), warp tile 64x32, fp16 m16n8k16,
// fp32 accumulators. Both 64-K chunks prefetched up front; ONE wait+barrier,
// then an uninterrupted 8-kstep compute stream (no mid-tile convoy).
// SW128 swizzle: byte_in_row ^= (row&7)<<4.
__global__ __launch_bounds__(256, 2)
void chamfer_mma_kernel() {
    extern __shared__ char smem[];
    const unsigned sbase = smem_u32(smem);

    const int t    = threadIdx.x;
    const int lane = t & 31;
    const int wid  = t >> 5;
    const int wi   = wid >> 2;    // 0..1 (64-row slab)
    const int wj   = wid & 3;     // 0..3 (32-col slab)
    const int g    = lane >> 2;   // 0..7
    const int tig  = lane & 3;    // 0..3

    const int b    = blockIdx.z;
    const int iblk = blockIdx.x * 128;
    const int jblk = blockIdx.y * 128;

    const __half* xph = g_xh + ((size_t)b * NN + iblk) * DD;
    const __half* yph = g_yh + ((size_t)b * MM + jblk) * DD;

    const unsigned swz = (unsigned)(lane & 7) << 4;
    const int arow_base = wi * 64 + (lane & 15);
    const int brow_base = wj * 32 + (lane & 7) + ((lane & 8) ? 8 : 0);
    const unsigned khalf = (lane & 16) ? 16u : 0u;

    #define PREFETCH(stage, chunk)                                                     \
        do {                                                                            \
            unsigned sdst = sbase + (stage) * STAGE_BYTES;                              \
            _Pragma("unroll")                                                           \
            for (int p = 0; p < 8; p++) {                                               \
                int idx = p * 256 + t;                                                  \
                int mat = p >> 2;                                                       \
                int row = (idx & 1023) >> 3;                                            \
                int c4  = idx & 7;                                                      \
                const __half* gsrc = (mat ? yph : xph) + (size_t)row * DD + (chunk) * 64 + c4 * 8; \
                unsigned d = sdst + mat * 16384 + row * 128 +                           \
                             (((unsigned)(c4 * 16)) ^ (((unsigned)(row & 7)) << 4));    \
                CP_ASYNC16(d, gsrc);                                                    \
            }                                                                           \
        } while (0)

    PREFETCH(0, 0);
    PREFETCH(1, 1);
    CP_COMMIT();

    // Norm loads in flight while tiles land.
    float x2v[4][2], y2v[4][2];
    #pragma unroll
    for (int mt = 0; mt < 4; mt++) {
        x2v[mt][0] = g_x2[(size_t)b * NN + iblk + wi * 64 + mt * 16 + g];
        x2v[mt][1] = g_x2[(size_t)b * NN + iblk + wi * 64 + mt * 16 + g + 8];
    }
    #pragma unroll
    for (int nt = 0; nt < 4; nt++) {
        y2v[nt][0] = g_y2[(size_t)b * MM + jblk + wj * 32 + nt * 8 + 2 * tig];
        y2v[nt][1] = g_y2[(size_t)b * MM + jblk + wj * 32 + nt * 8 + 2 * tig + 1];
    }

    float acc[4][4][4];
    #pragma unroll
    for (int mt = 0; mt < 4; mt++)
        #pragma unroll
        for (int nt = 0; nt < 4; nt++)
            #pragma unroll
            for (int r = 0; r < 4; r++) acc[mt][nt][r] = 0.0f;

    CP_WAIT(0);
    __syncthreads();   // single barrier: all 64KB visible to all threads

    #pragma unroll
    for (int c = 0; c < 2; c++) {
        const unsigned abase = sbase + c * STAGE_BYTES;
        const unsigned bbase = abase + 16384;

        #pragma unroll
        for (int ks = 0; ks < 4; ks++) {
            const unsigned k0b = ks * 32;
            unsigned af[4][4], bq[2][4];
            #pragma unroll
            for (int mt = 0; mt < 4; mt++) {
                int row = arow_base + mt * 16;
                ldsm4(af[mt], abase + row * 128 + ((k0b + khalf) ^ swz));
            }
            #pragma unroll
            for (int pr = 0; pr < 2; pr++) {
                int row = brow_base + pr * 16;
                ldsm4(bq[pr], bbase + row * 128 + ((k0b + khalf) ^ swz));
            }
            #pragma unroll
            for (int mt = 0; mt < 4; mt++)
                #pragma unroll
                for (int nt = 0; nt < 4; nt++)
                    mma_f16(acc[mt][nt], af[mt],
                            bq[nt >> 1][nt & 1], bq[nt >> 1][(nt & 1) + 2]);
        }
    }

    // ---- epilogue (verified R2/R4/R5/R6/R11/R13) ----
    const float INF = __int_as_float(0x7F800000);
    float rmin[4][2], cmin[4][2];
    #pragma unroll
    for (int a_ = 0; a_ < 4; a_++) { rmin[a_][0] = rmin[a_][1] = INF; cmin[a_][0] = cmin[a_][1] = INF; }

    #pragma unroll
    for (int mt = 0; mt < 4; mt++)
        #pragma unroll
        for (int nt = 0; nt < 4; nt++)
            #pragma unroll
            for (int rr = 0; rr < 2; rr++)
                #pragma unroll
                for (int cc = 0; cc < 2; cc++) {
                    float d2 = fmaxf(x2v[mt][rr] + y2v[nt][cc] - 2.0f * acc[mt][nt][rr * 2 + cc], 0.0f);
                    rmin[mt][rr] = fminf(rmin[mt][rr], d2);
                    cmin[nt][cc] = fminf(cmin[nt][cc], d2);
                }

    #pragma unroll
    for (int mt = 0; mt < 4; mt++)
        #pragma unroll
        for (int rr = 0; rr < 2; rr++) {
            float v = rmin[mt][rr];
            v = fminf(v, __shfl_xor_sync(0xFFFFFFFFu, v, 1));
            v = fminf(v, __shfl_xor_sync(0xFFFFFFFFu, v, 2));
            rmin[mt][rr] = v;
        }
    #pragma unroll
    for (int nt = 0; nt < 4; nt++)
        #pragma unroll
        for (int cc = 0; cc < 2; cc++) {
            float v = cmin[nt][cc];
            v = fminf(v, __shfl_xor_sync(0xFFFFFFFFu, v, 4));
            v = fminf(v, __shfl_xor_sync(0xFFFFFFFFu, v, 8));
            v = fminf(v, __shfl_xor_sync(0xFFFFFFFFu, v, 16));
            cmin[nt][cc] = v;
        }

    float* rowbuf = reinterpret_cast<float*>(smem);          // [128][4]
    float* colbuf = reinterpret_cast<float*>(smem) + 512;    // [128][2]
    __syncthreads();   // all warps done reading stage smem
    if (tig == 0) {
        #pragma unroll
        for (int mt = 0; mt < 4; mt++)
            #pragma unroll
            for (int rr = 0; rr < 2; rr++)
                rowbuf[(wi * 64 + mt * 16 + g + rr * 8) * 4 + wj] = rmin[mt][rr];
    }
    if (g == 0) {
        #pragma unroll
        for (int nt = 0; nt < 4; nt++)
            #pragma unroll
            for (int cc = 0; cc < 2; cc++)
                colbuf[(wj * 32 + nt * 8 + 2 * tig + cc) * 2 + wi] = cmin[nt][cc];
    }
    __syncthreads();

    if (t < 128) {
        float m = fminf(fminf(rowbuf[t * 4 + 0], rowbuf[t * 4 + 1]),
                        fminf(rowbuf[t * 4 + 2], rowbuf[t * 4 + 3]));
        atomicMin((int*)&g_rowmin[(size_t)b * NN + iblk + t], __float_as_int(m));
    } else {
        int j = t - 128;
        float m = fminf(colbuf[j * 2 + 0], colbuf[j * 2 + 1]);
        atomicMin((int*)&g_colmin[(size_t)b * MM + jblk + j], __float_as_int(m));
    }
}

// ---------------- fused final reduction (ticket finish) ----------------
__global__ void reduce_kernel(float* __restrict__ out) {
    __shared__ float smr[256];
    int tid = threadIdx.x;
    int i = blockIdx.x * 256 + tid;
    float s = sqrtf(g_rowmin[i]) + sqrtf(g_colmin[i]);
    smr[tid] = s;
    __syncthreads();
    for (int o = 128; o > 0; o >>= 1) {
        if (tid < o) smr[tid] += smr[tid + o];
        __syncthreads();
    }
    if (tid == 0) {
        atomicAdd(&g_sum, smr[0]);
        __threadfence();
        unsigned old = atomicAdd(&g_ticket, 1u);
        if (old == 127u) out[0] = g_sum / (float)(BB * NN);
    }
}

extern "C" void kernel_launch(void* const* d_in, const int* in_sizes, int n_in,
                              void* d_out, int out_size) {
    const float* x = (const float*)d_in[0];
    const float* y = (const float*)d_in[1];
    float* out = (float*)d_out;
    (void)in_sizes; (void)n_in; (void)out_size;

    cudaFuncSetAttribute(chamfer_mma_kernel, cudaFuncAttributeMaxDynamicSharedMemorySize, SMEM_TOTAL);

    int total_warps = (2 * BB * NN) / 4;   // 16384 warps, 4 rows each
    norms_conv_kernel<<<(total_warps * 32 + 255) / 256, 256>>>(x, y);

    dim3 grid(NN / 128, MM / 128, BB);
    chamfer_mma_kernel<<<grid, 256, SMEM_TOTAL>>>();

    reduce_kernel<<<128, 256>>>(out);
}

// round 16
// speedup vs baseline: 1.4255x; 1.0169x over previous
#include <cuda_runtime.h>
#include <cuda_fp16.h>
#include <math.h>

#define BB 8
#define NN 4096
#define MM 4096
#define DD 128
#define STAGE_BYTES 32768     // 2 mats * 128 rows * 128B (64 fp16 cols)
#define NSTAGE 2
#define SOFF_ROWBUF (NSTAGE * STAGE_BYTES)        // dedicated epilogue buffers
#define SOFF_COLBUF (SOFF_ROWBUF + 2048)
#define SMEM_TOTAL  (SOFF_COLBUF + 1024)          // 68608 B -> still 2 CTAs/SM

// ---------------- scratch ----------------
__device__ float g_rowmin[BB * NN];
__device__ float g_colmin[BB * MM];
__device__ float g_x2[BB * NN];
__device__ float g_y2[BB * MM];
__device__ float g_sum;
__device__ unsigned g_ticket;
__device__ __half g_xh[(size_t)BB * NN * DD];
__device__ __half g_yh[(size_t)BB * MM * DD];

// Four rows per warp: fp32 norms (exact), min-init, fp16 conversion, counter reset.
__global__ void norms_conv_kernel(const float* __restrict__ x, const float* __restrict__ y) {
    int gw   = (blockIdx.x * blockDim.x + threadIdx.x) >> 5;   // 0..16383
    int lane = threadIdx.x & 31;
    const float* src;
    float* dst;
    float* mins;
    __half* dsth;
    int r0;
    if (gw < (BB * NN) / 4) { src = x; dst = g_x2; mins = g_rowmin; dsth = g_xh; r0 = 4 * gw; }
    else { src = y; dst = g_y2; mins = g_colmin; dsth = g_yh; r0 = 4 * (gw - (BB * NN) / 4); }

    float4 v[4];
    #pragma unroll
    for (int k = 0; k < 4; k++)
        v[k] = *reinterpret_cast<const float4*>(src + (size_t)(r0 + k) * DD + lane * 4);

    float s[4];
    #pragma unroll
    for (int k = 0; k < 4; k++)
        s[k] = v[k].x * v[k].x + v[k].y * v[k].y + v[k].z * v[k].z + v[k].w * v[k].w;
    #pragma unroll
    for (int o = 16; o; o >>= 1) {
        #pragma unroll
        for (int k = 0; k < 4; k++)
            s[k] += __shfl_xor_sync(0xFFFFFFFFu, s[k], o);
    }

    #pragma unroll
    for (int k = 0; k < 4; k++) {
        __half2 h0 = __floats2half2_rn(v[k].x, v[k].y);
        __half2 h1 = __floats2half2_rn(v[k].z, v[k].w);
        uint2 u;
        u.x = *reinterpret_cast<unsigned*>(&h0);
        u.y = *reinterpret_cast<unsigned*>(&h1);
        *reinterpret_cast<uint2*>(dsth + (size_t)(r0 + k) * DD + lane * 4) = u;
    }

    if (lane < 4) {
        dst[r0 + lane]  = s[lane];
        mins[r0 + lane] = __int_as_float(0x7F800000);
    }
    if (blockIdx.x == 0 && threadIdx.x == 0) {
        g_sum = 0.0f;
        g_ticket = 0u;
    }
}

// ---------------- device helpers ----------------
__device__ __forceinline__ unsigned smem_u32(const void* p) {
    unsigned a;
    asm("{ .reg .u64 t; cvta.to.shared.u64 t, %1; cvt.u32.u64 %0, t; }" : "=r"(a) : "l"(p));
    return a;
}

__device__ __forceinline__ void mma_f16(float* c, const unsigned* a, unsigned b0, unsigned b1) {
    asm volatile(
        "mma.sync.aligned.m16n8k16.row.col.f32.f16.f16.f32 "
        "{%0,%1,%2,%3}, {%4,%5,%6,%7}, {%8,%9}, {%0,%1,%2,%3};"
        : "+f"(c[0]), "+f"(c[1]), "+f"(c[2]), "+f"(c[3])
        : "r"(a[0]), "r"(a[1]), "r"(a[2]), "r"(a[3]), "r"(b0), "r"(b1));
}

__device__ __forceinline__ void ldsm4(unsigned* r, unsigned addr) {
    asm volatile("ldmatrix.sync.aligned.m8n8.x4.shared.b16 {%0,%1,%2,%3}, [%4];"
                 : "=r"(r[0]), "=r"(r[1]), "=r"(r[2]), "=r"(r[3]) : "r"(addr));
}

#define CP_ASYNC16(dst, src) \
    asm volatile("cp.async.cg.shared.global [%0], [%1], 16;" :: "r"(dst), "l"(src))
#define CP_COMMIT() asm volatile("cp.async.commit_group;" ::: "memory")
#define CP_WAIT(n)  asm volatile("cp.async.wait_group %0;" :: "n"(n) : "memory")

// ---------------- main kernel ----------------
// 128x128 tile, 256 threads (8 warps 2x4), warp tile 64x32, fp16 m16n8k16,
// fp32 accumulators. Both 64-K chunks prefetched up front; ONE wait+barrier,
// uninterrupted 8-kstep compute stream; epilogue uses DEDICATED smem so the
// pre-write barrier is gone. SW128 swizzle: byte_in_row ^= (row&7)<<4.
__global__ __launch_bounds__(256, 2)
void chamfer_mma_kernel() {
    extern __shared__ char smem[];
    const unsigned sbase = smem_u32(smem);

    const int t    = threadIdx.x;
    const int lane = t & 31;
    const int wid  = t >> 5;
    const int wi   = wid >> 2;    // 0..1 (64-row slab)
    const int wj   = wid & 3;     // 0..3 (32-col slab)
    const int g    = lane >> 2;   // 0..7
    const int tig  = lane & 3;    // 0..3

    const int b    = blockIdx.z;
    const int iblk = blockIdx.x * 128;
    const int jblk = blockIdx.y * 128;

    const __half* xph = g_xh + ((size_t)b * NN + iblk) * DD;
    const __half* yph = g_yh + ((size_t)b * MM + jblk) * DD;

    const unsigned swz = (unsigned)(lane & 7) << 4;
    const int arow_base = wi * 64 + (lane & 15);
    const int brow_base = wj * 32 + (lane & 7) + ((lane & 8) ? 8 : 0);
    const unsigned khalf = (lane & 16) ? 16u : 0u;

    #define PREFETCH(stage, chunk)                                                     \
        do {                                                                            \
            unsigned sdst = sbase + (stage) * STAGE_BYTES;                              \
            _Pragma("unroll")                                                           \
            for (int p = 0; p < 8; p++) {                                               \
                int idx = p * 256 + t;                                                  \
                int mat = p >> 2;                                                       \
                int row = (idx & 1023) >> 3;                                            \
                int c4  = idx & 7;                                                      \
                const __half* gsrc = (mat ? yph : xph) + (size_t)row * DD + (chunk) * 64 + c4 * 8; \
                unsigned d = sdst + mat * 16384 + row * 128 +                           \
                             (((unsigned)(c4 * 16)) ^ (((unsigned)(row & 7)) << 4));    \
                CP_ASYNC16(d, gsrc);                                                    \
            }                                                                           \
        } while (0)

    PREFETCH(0, 0);
    PREFETCH(1, 1);
    CP_COMMIT();

    // Norm loads in flight while tiles land.
    float x2v[4][2], y2v[4][2];
    #pragma unroll
    for (int mt = 0; mt < 4; mt++) {
        x2v[mt][0] = g_x2[(size_t)b * NN + iblk + wi * 64 + mt * 16 + g];
        x2v[mt][1] = g_x2[(size_t)b * NN + iblk + wi * 64 + mt * 16 + g + 8];
    }
    #pragma unroll
    for (int nt = 0; nt < 4; nt++) {
        y2v[nt][0] = g_y2[(size_t)b * MM + jblk + wj * 32 + nt * 8 + 2 * tig];
        y2v[nt][1] = g_y2[(size_t)b * MM + jblk + wj * 32 + nt * 8 + 2 * tig + 1];
    }

    float acc[4][4][4];
    #pragma unroll
    for (int mt = 0; mt < 4; mt++)
        #pragma unroll
        for (int nt = 0; nt < 4; nt++)
            #pragma unroll
            for (int r = 0; r < 4; r++) acc[mt][nt][r] = 0.0f;

    CP_WAIT(0);
    __syncthreads();   // single barrier: all 64KB visible to all threads

    #pragma unroll
    for (int c = 0; c < 2; c++) {
        const unsigned abase = sbase + c * STAGE_BYTES;
        const unsigned bbase = abase + 16384;

        #pragma unroll
        for (int ks = 0; ks < 4; ks++) {
            const unsigned k0b = ks * 32;
            unsigned af[4][4], bq[2][4];
            #pragma unroll
            for (int mt = 0; mt < 4; mt++) {
                int row = arow_base + mt * 16;
                ldsm4(af[mt], abase + row * 128 + ((k0b + khalf) ^ swz));
            }
            #pragma unroll
            for (int pr = 0; pr < 2; pr++) {
                int row = brow_base + pr * 16;
                ldsm4(bq[pr], bbase + row * 128 + ((k0b + khalf) ^ swz));
            }
            #pragma unroll
            for (int mt = 0; mt < 4; mt++)
                #pragma unroll
                for (int nt = 0; nt < 4; nt++)
                    mma_f16(acc[mt][nt], af[mt],
                            bq[nt >> 1][nt & 1], bq[nt >> 1][(nt & 1) + 2]);
        }
    }

    // ---- epilogue (verified math; dedicated buffers, no pre-write barrier) ----
    const float INF = __int_as_float(0x7F800000);
    float rmin[4][2], cmin[4][2];
    #pragma unroll
    for (int a_ = 0; a_ < 4; a_++) { rmin[a_][0] = rmin[a_][1] = INF; cmin[a_][0] = cmin[a_][1] = INF; }

    #pragma unroll
    for (int mt = 0; mt < 4; mt++)
        #pragma unroll
        for (int nt = 0; nt < 4; nt++)
            #pragma unroll
            for (int rr = 0; rr < 2; rr++)
                #pragma unroll
                for (int cc = 0; cc < 2; cc++) {
                    float d2 = fmaxf(x2v[mt][rr] + y2v[nt][cc] - 2.0f * acc[mt][nt][rr * 2 + cc], 0.0f);
                    rmin[mt][rr] = fminf(rmin[mt][rr], d2);
                    cmin[nt][cc] = fminf(cmin[nt][cc], d2);
                }

    #pragma unroll
    for (int mt = 0; mt < 4; mt++)
        #pragma unroll
        for (int rr = 0; rr < 2; rr++) {
            float v = rmin[mt][rr];
            v = fminf(v, __shfl_xor_sync(0xFFFFFFFFu, v, 1));
            v = fminf(v, __shfl_xor_sync(0xFFFFFFFFu, v, 2));
            rmin[mt][rr] = v;
        }
    #pragma unroll
    for (int nt = 0; nt < 4; nt++)
        #pragma unroll
        for (int cc = 0; cc < 2; cc++) {
            float v = cmin[nt][cc];
            v = fminf(v, __shfl_xor_sync(0xFFFFFFFFu, v, 4));
            v = fminf(v, __shfl_xor_sync(0xFFFFFFFFu, v, 8));
            v = fminf(v, __shfl_xor_sync(0xFFFFFFFFu, v, 16));
            cmin[nt][cc] = v;
        }

    float* rowbuf = reinterpret_cast<float*>(smem + SOFF_ROWBUF);   // [128][4]
    float* colbuf = reinterpret_cast<float*>(smem + SOFF_COLBUF);   // [128][2]
    if (tig == 0) {
        #pragma unroll
        for (int mt = 0; mt < 4; mt++)
            #pragma unroll
            for (int rr = 0; rr < 2; rr++)
                rowbuf[(wi * 64 + mt * 16 + g + rr * 8) * 4 + wj] = rmin[mt][rr];
    }
    if (g == 0) {
        #pragma unroll
        for (int nt = 0; nt < 4; nt++)
            #pragma unroll
            for (int cc = 0; cc < 2; cc++)
                colbuf[(wj * 32 + nt * 8 + 2 * tig + cc) * 2 + wi] = cmin[nt][cc];
    }
    __syncthreads();   // writes visible before cross-warp reads

    if (t < 128) {
        float m = fminf(fminf(rowbuf[t * 4 + 0], rowbuf[t * 4 + 1]),
                        fminf(rowbuf[t * 4 + 2], rowbuf[t * 4 + 3]));
        atomicMin((int*)&g_rowmin[(size_t)b * NN + iblk + t], __float_as_int(m));
    } else {
        int j = t - 128;
        float m = fminf(colbuf[j * 2 + 0], colbuf[j * 2 + 1]);
        atomicMin((int*)&g_colmin[(size_t)b * MM + jblk + j], __float_as_int(m));
    }
}

// ---------------- fused final reduction (ticket finish) ----------------
__global__ void reduce_kernel(float* __restrict__ out) {
    __shared__ float smr[256];
    int tid = threadIdx.x;
    int i = blockIdx.x * 256 + tid;
    float s = sqrtf(g_rowmin[i]) + sqrtf(g_colmin[i]);
    smr[tid] = s;
    __syncthreads();
    for (int o = 128; o > 0; o >>= 1) {
        if (tid < o) smr[tid] += smr[tid + o];
        __syncthreads();
    }
    if (tid == 0) {
        atomicAdd(&g_sum, smr[0]);
        __threadfence();
        unsigned old = atomicAdd(&g_ticket, 1u);
        if (old == 127u) out[0] = g_sum / (float)(BB * NN);
    }
}

extern "C" void kernel_launch(void* const* d_in, const int* in_sizes, int n_in,
                              void* d_out, int out_size) {
    const float* x = (const float*)d_in[0];
    const float* y = (const float*)d_in[1];
    float* out = (float*)d_out;
    (void)in_sizes; (void)n_in; (void)out_size;

    cudaFuncSetAttribute(chamfer_mma_kernel, cudaFuncAttributeMaxDynamicSharedMemorySize, SMEM_TOTAL);

    int total_warps = (2 * BB * NN) / 4;   // 16384 warps, 4 rows each
    norms_conv_kernel<<<(total_warps * 32 + 255) / 256, 256>>>(x, y);

    dim3 grid(NN / 128, MM / 128, BB);
    chamfer_mma_kernel<<<grid, 256, SMEM_TOTAL>>>();

    reduce_kernel<<<128, 256>>>(out);
}